// round 7
// baseline (speedup 1.0000x reference)
#include <cuda_runtime.h>
#include <cuda_bf16.h>
#include <cstdint>

#define DDIM 512
#define KC   512
#define TMR  64

// smem layout (bytes)
#define OFF_ZS  0         // 64 rows x 1024B bf16, swizzled
#define OFF_PS  65536     // 2 x 16384 P chunk double buffer; reused as 32KB cand table
#define OFF_PN  98304     // 512 f32
#define OFF_ZN  100352    // 64 f32
#define SMEM_SZ 100608

typedef unsigned long long ull;

static __device__ __align__(128) __nv_bfloat16 g_pb[KC * DDIM];
static __device__ float g_pn[KC];

__device__ __forceinline__ uint32_t smem_u32(const void* p) {
    uint32_t a;
    asm("{ .reg .u64 t; cvta.to.shared.u64 t, %1; cvt.u32.u64 %0, t; }" : "=r"(a) : "l"(p));
    return a;
}
__device__ __forceinline__ unsigned fenc(float f) {
    unsigned b = __float_as_uint(f);
    return (b & 0x80000000u) ? ~b : (b | 0x80000000u);
}
__device__ __forceinline__ uint32_t bf2(float a, float b) {
    __nv_bfloat162 h = __floats2bfloat162_rn(a, b);
    return *reinterpret_cast<uint32_t*>(&h);
}
__device__ __forceinline__ void ldsm_x4(uint32_t* r, uint32_t addr) {
    asm volatile("ldmatrix.sync.aligned.m8n8.x4.shared.b16 {%0,%1,%2,%3}, [%4];"
        : "=r"(r[0]), "=r"(r[1]), "=r"(r[2]), "=r"(r[3]) : "r"(addr));
}
__device__ __forceinline__ void mma_bf16(float* c, const uint32_t* a, uint32_t b0, uint32_t b1) {
    asm volatile("mma.sync.aligned.m16n8k16.row.col.f32.bf16.bf16.f32 "
        "{%0,%1,%2,%3}, {%4,%5,%6,%7}, {%8,%9}, {%0,%1,%2,%3};"
        : "+f"(c[0]), "+f"(c[1]), "+f"(c[2]), "+f"(c[3])
        : "r"(a[0]), "r"(a[1]), "r"(a[2]), "r"(a[3]), "r"(b0), "r"(b1));
}
#define CP_COMMIT() asm volatile("cp.async.commit_group;" ::: "memory")

// ---------------- P prep: bf16 copy + norms ----------------
__global__ void p_prep(const float* __restrict__ P) {
    int row = blockIdx.x * 8 + (threadIdx.x >> 5);
    if (row >= KC) return;
    int lane = threadIdx.x & 31;
    const float4* pr = reinterpret_cast<const float4*>(P) + (size_t)row * 128;
    uint2* pb = reinterpret_cast<uint2*>(g_pb) + (size_t)row * 128;
    float s = 0.f;
#pragma unroll
    for (int i = 0; i < 4; ++i) {
        float4 v = pr[lane + 32 * i];
        s += v.x * v.x + v.y * v.y + v.z * v.z + v.w * v.w;
        uint2 o; o.x = bf2(v.x, v.y); o.y = bf2(v.z, v.w);
        pb[lane + 32 * i] = o;
    }
#pragma unroll
    for (int o = 16; o; o >>= 1) s += __shfl_xor_sync(0xffffffffu, s, o);
    if (lane == 0) g_pn[row] = s;
}

// ---------------- P chunk loader: 256 codes x 32 k-halfs = 16KB ----------------
// row pitch 64B (4 x 16B chunks), swizzle: phys_chunk = j ^ ((n>>1)&3)
__device__ __forceinline__ void load_chunk(uint32_t sb, int i, int tid) {
    const int ct = i >> 4, kc = i & 15, buf = i & 1;
    const int n = tid;                       // one code per thread
    const __nv_bfloat16* src = g_pb + (size_t)(ct * 256 + n) * DDIM + kc * 32;
    uint32_t dst = sb + OFF_PS + buf * 16384 + n * 64;
    const int sx = (n >> 1) & 3;
#pragma unroll
    for (int j = 0; j < 4; ++j) {
        uint32_t d = dst + (uint32_t)((j ^ sx) << 4);
        asm volatile("cp.async.cg.shared.global [%0], [%1], 16;"
                     :: "r"(d), "l"((const void*)(src + j * 8)) : "memory");
    }
}

// ---------------- fused main kernel: 256 threads, 8 warps, 2 CTAs/SM ----------------
__global__ void __launch_bounds__(256, 2) vq_main(
    const float* __restrict__ z, const float* __restrict__ Pf,
    float* __restrict__ zhat, float* __restrict__ ztil, float* __restrict__ idxf)
{
    extern __shared__ char smem[];
    const uint32_t sb = smem_u32(smem);
    const int tid = threadIdx.x, wid = tid >> 5, lane = tid & 31;
    const int row0 = blockIdx.x * TMR;
    const int m0 = (wid & 1) * 32;        // 2 m-warps x 32 rows
    const int n0 = (wid >> 1) * 64;       // 4 n-warps x 64 cols

    float* s_pn = reinterpret_cast<float*>(smem + OFF_PN);
    float* s_zn = reinterpret_cast<float*>(smem + OFF_ZN);

    // prefetch first P chunk early
    load_chunk(sb, 0, tid);
    CP_COMMIT();

    for (int i = tid; i < KC; i += 256) s_pn[i] = g_pn[i];

    // prologue: z -> bf16 smem (swizzled, 1024B rows), fused squared norm (4 thr/row)
    {
        const int r = tid >> 2, q = tid & 3;
        const float4* zr = reinterpret_cast<const float4*>(z)
                         + (size_t)(row0 + r) * 128 + q * 32;
        float s = 0.f;
#pragma unroll 4
        for (int c = 0; c < 16; ++c) {
            float4 v0 = zr[c * 2], v1 = zr[c * 2 + 1];
            s += v0.x * v0.x + v0.y * v0.y + v0.z * v0.z + v0.w * v0.w;
            s += v1.x * v1.x + v1.y * v1.y + v1.z * v1.z + v1.w * v1.w;
            uint4 o;
            o.x = bf2(v0.x, v0.y); o.y = bf2(v0.z, v0.w);
            o.z = bf2(v1.x, v1.y); o.w = bf2(v1.z, v1.w);
            int chunk = (q * 16 + c) ^ (r & 7);
            *reinterpret_cast<uint4*>(smem + OFF_ZS + r * 1024 + chunk * 16) = o;
        }
        s += __shfl_xor_sync(0xffffffffu, s, 1);
        s += __shfl_xor_sync(0xffffffffu, s, 2);
        if (q == 0) s_zn[r] = s;
    }

    float acc[2][8][4];
    float bd[4][4];     // per row-slot top-4 approx dists (pn - 2*dot)
    int   bi[4][4];
#pragma unroll
    for (int s = 0; s < 4; ++s)
#pragma unroll
        for (int j = 0; j < 4; ++j) { bd[s][j] = __int_as_float(0x7f800000); bi[s][j] = j; }
#pragma unroll
    for (int mt = 0; mt < 2; ++mt)
#pragma unroll
        for (int nt = 0; nt < 8; ++nt)
#pragma unroll
            for (int e = 0; e < 4; ++e) acc[mt][nt][e] = 0.f;

    // main pipeline: 32 chunks = 2 col-tiles x 16 k-chunks (k=32), double-buffered
    for (int i = 0; i < 32; ++i) {
        if (i < 31) { load_chunk(sb, i + 1, tid); CP_COMMIT(); }
        if (i < 31) asm volatile("cp.async.wait_group 1;" ::: "memory");
        else        asm volatile("cp.async.wait_group 0;" ::: "memory");
        __syncthreads();

        const int ct = i >> 4, kcl = i & 15;
        const uint32_t pbase = sb + OFF_PS + (i & 1) * 16384;
#pragma unroll
        for (int kk = 0; kk < 2; ++kk) {
            const int kg = kcl * 32 + kk * 16;
            uint32_t a[2][4];
#pragma unroll
            for (int mt = 0; mt < 2; ++mt) {
                int rg = m0 + mt * 16 + (lane & 15);
                int kq = kg + ((lane >> 4) << 3);
                uint32_t ad = sb + OFF_ZS + rg * 1024
                            + (uint32_t)((((kq >> 3) ^ (rg & 7))) << 4);
                ldsm_x4(a[mt], ad);
            }
#pragma unroll
            for (int ntp = 0; ntp < 4; ++ntp) {
                // x4: m0/m1 = k-halves of n8 tile (2ntp), m2/m3 = tile (2ntp+1)
                int nl = n0 + ntp * 16 + ((lane >> 4) << 3) + (lane & 7);
                int kq8 = kk * 2 + ((lane >> 3) & 1);
                uint32_t bdad = pbase + nl * 64
                              + (uint32_t)(((kq8 ^ ((nl >> 1) & 3))) << 4);
                uint32_t rb[4];
                ldsm_x4(rb, bdad);
#pragma unroll
                for (int mt = 0; mt < 2; ++mt) {
                    mma_bf16(acc[mt][ntp * 2],     a[mt], rb[0], rb[1]);
                    mma_bf16(acc[mt][ntp * 2 + 1], a[mt], rb[2], rb[3]);
                }
            }
        }

        if (kcl == 15) {
            // merge col-tile dists (pn - 2*dot, row-constant zn dropped) into top-4
            const int ctbase = ct * 256;
#pragma unroll
            for (int mt = 0; mt < 2; ++mt)
#pragma unroll
                for (int half = 0; half < 2; ++half) {
                    const int s = mt * 2 + half;
#pragma unroll
                    for (int nt = 0; nt < 8; ++nt)
#pragma unroll
                        for (int e = 0; e < 2; ++e) {
                            const int col = ctbase + n0 + nt * 8 + (lane & 3) * 2 + e;
                            float d = __fmaf_rn(-2.f, acc[mt][nt][half * 2 + e], s_pn[col]);
                            if (d < bd[s][3]) {
                                bd[s][3] = d; bi[s][3] = col;
                                if (bd[s][3] < bd[s][2]) { float t = bd[s][2]; bd[s][2] = bd[s][3]; bd[s][3] = t; int ti = bi[s][2]; bi[s][2] = bi[s][3]; bi[s][3] = ti; }
                                if (bd[s][2] < bd[s][1]) { float t = bd[s][1]; bd[s][1] = bd[s][2]; bd[s][2] = t; int ti = bi[s][1]; bi[s][1] = bi[s][2]; bi[s][2] = ti; }
                                if (bd[s][1] < bd[s][0]) { float t = bd[s][0]; bd[s][0] = bd[s][1]; bd[s][1] = t; int ti = bi[s][0]; bi[s][0] = bi[s][1]; bi[s][1] = ti; }
                            }
                            acc[mt][nt][half * 2 + e] = 0.f;
                        }
                }
        }
        __syncthreads();
    }

    // dump per-lane top-4 (packed keys) into cand table: 64 rows x 16 slots x 4
    ull* tab = reinterpret_cast<ull*>(smem + OFF_PS);
    {
        const int slot = (wid >> 1) * 4 + (lane & 3);
#pragma unroll
        for (int s = 0; s < 4; ++s) {
            const int mt = s >> 1, half = s & 1;
            const int rloc = m0 + mt * 16 + half * 8 + (lane >> 2);
#pragma unroll
            for (int j = 0; j < 4; ++j)
                tab[(rloc * 16 + slot) * 4 + j] =
                    ((ull)fenc(bd[s][j]) << 32) | (unsigned)bi[s][j];
        }
    }
    __syncthreads();

    // per-row: global top-4 of 64 keys -> exact fp32 rescore -> winner -> outputs
    const float4* z4 = reinterpret_cast<const float4*>(z);
    const float4* P4 = reinterpret_cast<const float4*>(Pf);
    float4* zh4 = reinterpret_cast<float4*>(zhat);
    float4* zt4 = reinterpret_cast<float4*>(ztil);

    for (int rr = 0; rr < 8; ++rr) {
        const int r = wid * 8 + rr;
        float4 za[4];
#pragma unroll
        for (int q = 0; q < 4; ++q)
            za[q] = z4[(size_t)(row0 + r) * 128 + q * 32 + lane];
        const float zn = s_zn[r];

        ull k0_ = tab[r * 64 + lane];
        ull k1_ = tab[r * 64 + 32 + lane];
        ull winkey = ~0ull;
#pragma unroll
        for (int it = 0; it < 4; ++it) {
            ull m = k0_ < k1_ ? k0_ : k1_;
#pragma unroll
            for (int o = 16; o; o >>= 1) {
                ull om = __shfl_xor_sync(0xffffffffu, m, o);
                m = om < m ? om : m;
            }
            const int c = (int)(m & 511ull);
            if (k0_ == m) k0_ = ~0ull;
            if (k1_ == m) k1_ = ~0ull;

            float s_ = 0.f;
#pragma unroll
            for (int q = 0; q < 4; ++q) {
                float4 pb = P4[(size_t)c * 128 + q * 32 + lane];
                s_ = fmaf(za[q].x, pb.x, s_);
                s_ = fmaf(za[q].y, pb.y, s_);
                s_ = fmaf(za[q].z, pb.z, s_);
                s_ = fmaf(za[q].w, pb.w, s_);
            }
#pragma unroll
            for (int o = 16; o; o >>= 1) s_ += __shfl_xor_sync(0xffffffffu, s_, o);
            float t = __fadd_rn(zn, s_pn[c]);
            float dist = __fadd_rn(t, -2.0f * s_);
            ull key = ((ull)fenc(dist) << 32) | (unsigned)c;
            winkey = key < winkey ? key : winkey;
        }
        const int c = (int)(winkey & 511ull);
#pragma unroll
        for (int q = 0; q < 4; ++q) {
            float4 pv = P4[(size_t)c * 128 + q * 32 + lane];
            size_t go = (size_t)(row0 + r) * 128 + q * 32 + lane;
            float4 hv;
            hv.x = __fadd_rn(__fmul_rn(0.7f, za[q].x), __fmul_rn(0.3f, pv.x));
            hv.y = __fadd_rn(__fmul_rn(0.7f, za[q].y), __fmul_rn(0.3f, pv.y));
            hv.z = __fadd_rn(__fmul_rn(0.7f, za[q].z), __fmul_rn(0.3f, pv.z));
            hv.w = __fadd_rn(__fmul_rn(0.7f, za[q].w), __fmul_rn(0.3f, pv.w));
            zt4[go] = pv;
            zh4[go] = hv;
        }
        if (lane == 0) idxf[row0 + r] = (float)c;
    }
}

extern "C" void kernel_launch(void* const* d_in, const int* in_sizes, int n_in,
                              void* d_out, int out_size)
{
    const float* z = (const float*)d_in[0];
    const float* P = (const float*)d_in[1];
    int N = in_sizes[0] / DDIM;   // 131072

    float* out  = (float*)d_out;
    float* zhat = out;
    float* ztil = out + (size_t)N * DDIM;
    float* idxf = out + 2 * (size_t)N * DDIM;

    cudaFuncSetAttribute(vq_main, cudaFuncAttributeMaxDynamicSharedMemorySize, SMEM_SZ);

    p_prep<<<KC / 8, 256>>>(P);
    vq_main<<<N / TMR, 256, SMEM_SZ>>>(z, P, zhat, ztil, idxf);
}

// round 8
// speedup vs baseline: 1.1645x; 1.1645x over previous
#include <cuda_runtime.h>
#include <cuda_bf16.h>
#include <cstdint>

#define DDIM 512
#define KC   512
#define TMR  128

// smem layout (bytes)
#define OFF_ZS  0         // 128 rows x 1024B bf16, swizzled
#define OFF_PS  131072    // 3 x 32768 P chunk buffers; reused as 64KB cand table
#define OFF_PN  229376    // 512 f32
#define OFF_ZN  231424    // 128 f32
#define SMEM_SZ 231936

typedef unsigned long long ull;

static __device__ __align__(128) __nv_bfloat16 g_pb[KC * DDIM];
static __device__ float g_pn[KC];

__device__ __forceinline__ uint32_t smem_u32(const void* p) {
    uint32_t a;
    asm("{ .reg .u64 t; cvta.to.shared.u64 t, %1; cvt.u32.u64 %0, t; }" : "=r"(a) : "l"(p));
    return a;
}
__device__ __forceinline__ unsigned fenc(float f) {
    unsigned b = __float_as_uint(f);
    return (b & 0x80000000u) ? ~b : (b | 0x80000000u);
}
__device__ __forceinline__ uint32_t bf2(float a, float b) {
    __nv_bfloat162 h = __floats2bfloat162_rn(a, b);
    return *reinterpret_cast<uint32_t*>(&h);
}
__device__ __forceinline__ void ldsm_x4(uint32_t* r, uint32_t addr) {
    asm volatile("ldmatrix.sync.aligned.m8n8.x4.shared.b16 {%0,%1,%2,%3}, [%4];"
        : "=r"(r[0]), "=r"(r[1]), "=r"(r[2]), "=r"(r[3]) : "r"(addr));
}
__device__ __forceinline__ void mma_bf16(float* c, const uint32_t* a, uint32_t b0, uint32_t b1) {
    asm volatile("mma.sync.aligned.m16n8k16.row.col.f32.bf16.bf16.f32 "
        "{%0,%1,%2,%3}, {%4,%5,%6,%7}, {%8,%9}, {%0,%1,%2,%3};"
        : "+f"(c[0]), "+f"(c[1]), "+f"(c[2]), "+f"(c[3])
        : "r"(a[0]), "r"(a[1]), "r"(a[2]), "r"(a[3]), "r"(b0), "r"(b1));
}
#define CP_COMMIT() asm volatile("cp.async.commit_group;" ::: "memory")

// ---------------- P prep: bf16 copy + norms ----------------
__global__ void p_prep(const float* __restrict__ P) {
    int row = blockIdx.x * 8 + (threadIdx.x >> 5);
    if (row >= KC) return;
    int lane = threadIdx.x & 31;
    const float4* pr = reinterpret_cast<const float4*>(P) + (size_t)row * 128;
    uint2* pb = reinterpret_cast<uint2*>(g_pb) + (size_t)row * 128;
    float s = 0.f;
#pragma unroll
    for (int i = 0; i < 4; ++i) {
        float4 v = pr[lane + 32 * i];
        s += v.x * v.x + v.y * v.y + v.z * v.z + v.w * v.w;
        uint2 o; o.x = bf2(v.x, v.y); o.y = bf2(v.z, v.w);
        pb[lane + 32 * i] = o;
    }
#pragma unroll
    for (int o = 16; o; o >>= 1) s += __shfl_xor_sync(0xffffffffu, s, o);
    if (lane == 0) g_pn[row] = s;
}

// ---------------- P chunk loader (cp.async, swizzled), 512 threads ----------------
__device__ __forceinline__ void load_chunk(uint32_t sb, int i, int tid) {
    const int ct = i >> 3, kc = i & 7, buf = i % 3;
    const int n = tid >> 1, half = tid & 1;       // 256 codes, 2 threads/code
    const __nv_bfloat16* src = g_pb + (size_t)(ct * 256 + n) * DDIM + kc * 64 + half * 32;
    uint32_t dst = sb + OFF_PS + buf * 32768 + n * 128;
#pragma unroll
    for (int j = 0; j < 4; ++j) {
        int c = half * 4 + j;
        uint32_t d = dst + (uint32_t)((c ^ (n & 7)) << 4);
        asm volatile("cp.async.cg.shared.global [%0], [%1], 16;"
                     :: "r"(d), "l"((const void*)(src + j * 8)) : "memory");
    }
}

// ---------------- fused main kernel: 512 threads, 16 warps ----------------
__global__ void __launch_bounds__(512, 1) vq_main(
    const float* __restrict__ z, const float* __restrict__ Pf,
    float* __restrict__ zhat, float* __restrict__ ztil, float* __restrict__ idxf)
{
    extern __shared__ char smem[];
    const uint32_t sb = smem_u32(smem);
    const int tid = threadIdx.x, wid = tid >> 5, lane = tid & 31;
    const int row0 = blockIdx.x * TMR;
    const int m0 = (wid & 3) * 32;        // 4 m-warps x 32 rows
    const int n0 = (wid >> 2) * 64;       // 4 n-warps x 64 cols

    float* s_pn = reinterpret_cast<float*>(smem + OFF_PN);
    float* s_zn = reinterpret_cast<float*>(smem + OFF_ZN);

    // prefetch first P chunk before the z prologue
    load_chunk(sb, 0, tid);
    CP_COMMIT();

    for (int i = tid; i < KC; i += 512) s_pn[i] = g_pn[i];

    // prologue: z -> bf16 smem (swizzled), fused squared norm (4 threads/row)
    {
        const int r = tid >> 2, q = tid & 3;
        const float4* zr = reinterpret_cast<const float4*>(z)
                         + (size_t)(row0 + r) * 128 + q * 32;
        float s = 0.f;
#pragma unroll 4
        for (int c = 0; c < 16; ++c) {
            float4 v0 = zr[c * 2], v1 = zr[c * 2 + 1];
            s += v0.x * v0.x + v0.y * v0.y + v0.z * v0.z + v0.w * v0.w;
            s += v1.x * v1.x + v1.y * v1.y + v1.z * v1.z + v1.w * v1.w;
            uint4 o;
            o.x = bf2(v0.x, v0.y); o.y = bf2(v0.z, v0.w);
            o.z = bf2(v1.x, v1.y); o.w = bf2(v1.z, v1.w);
            int chunk = (q * 16 + c) ^ (r & 7);
            *reinterpret_cast<uint4*>(smem + OFF_ZS + r * 1024 + chunk * 16) = o;
        }
        s += __shfl_xor_sync(0xffffffffu, s, 1);
        s += __shfl_xor_sync(0xffffffffu, s, 2);
        if (q == 0) s_zn[r] = s;
    }

    // prime second chunk
    load_chunk(sb, 1, tid);
    CP_COMMIT();

    float acc[2][8][4];
    float bdv[4][4];    // per row-slot top-4 approx dists (pn - 2*dot)
    int   biv[4][4];
#pragma unroll
    for (int s = 0; s < 4; ++s)
#pragma unroll
        for (int j = 0; j < 4; ++j) { bdv[s][j] = __int_as_float(0x7f800000); biv[s][j] = j; }
#pragma unroll
    for (int mt = 0; mt < 2; ++mt)
#pragma unroll
        for (int nt = 0; nt < 8; ++nt)
#pragma unroll
            for (int e = 0; e < 4; ++e) acc[mt][nt][e] = 0.f;

    // main pipeline: 16 chunks = 2 col-tiles x 8 k-chunks, triple-buffered,
    // ONE barrier per chunk: wait(i) -> sync -> compute(i) -> issue load(i+2)
    for (int i = 0; i < 16; ++i) {
        if (i < 14) asm volatile("cp.async.wait_group 1;" ::: "memory");
        else        asm volatile("cp.async.wait_group 0;" ::: "memory");
        __syncthreads();

        const int ct = i >> 3, kcl = i & 7;
        const uint32_t pbase = sb + OFF_PS + (uint32_t)(i % 3) * 32768;
#pragma unroll
        for (int kk = 0; kk < 4; ++kk) {
            const int kg = kcl * 64 + kk * 16;
            uint32_t a[2][4];
#pragma unroll
            for (int mt = 0; mt < 2; ++mt) {
                int rg = m0 + mt * 16 + (lane & 15);
                int kq = kg + ((lane >> 4) << 3);
                uint32_t ad = sb + OFF_ZS + rg * 1024
                            + (uint32_t)((((kq >> 3) ^ (rg & 7))) << 4);
                ldsm_x4(a[mt], ad);
            }
#pragma unroll
            for (int ntp = 0; ntp < 4; ++ntp) {
                int nl = n0 + ntp * 16 + ((lane >> 4) << 3) + (lane & 7);
                int kq8 = kk * 2 + ((lane >> 3) & 1);
                uint32_t bdad = pbase + nl * 128
                              + (uint32_t)(((kq8 ^ (nl & 7))) << 4);
                uint32_t rb[4];
                ldsm_x4(rb, bdad);
#pragma unroll
                for (int mt = 0; mt < 2; ++mt) {
                    mma_bf16(acc[mt][ntp * 2],     a[mt], rb[0], rb[1]);
                    mma_bf16(acc[mt][ntp * 2 + 1], a[mt], rb[2], rb[3]);
                }
            }
        }

        if (kcl == 7) {
            // merge col-tile dists (pn - 2*dot; row-constant zn dropped) into top-4
            const int ctbase = ct * 256;
#pragma unroll
            for (int mt = 0; mt < 2; ++mt)
#pragma unroll
                for (int half = 0; half < 2; ++half) {
                    const int s = mt * 2 + half;
#pragma unroll
                    for (int nt = 0; nt < 8; ++nt)
#pragma unroll
                        for (int e = 0; e < 2; ++e) {
                            const int col = ctbase + n0 + nt * 8 + (lane & 3) * 2 + e;
                            float d = __fmaf_rn(-2.f, acc[mt][nt][half * 2 + e], s_pn[col]);
                            if (d < bdv[s][3]) {
                                bdv[s][3] = d; biv[s][3] = col;
                                if (bdv[s][3] < bdv[s][2]) { float t = bdv[s][2]; bdv[s][2] = bdv[s][3]; bdv[s][3] = t; int ti = biv[s][2]; biv[s][2] = biv[s][3]; biv[s][3] = ti; }
                                if (bdv[s][2] < bdv[s][1]) { float t = bdv[s][1]; bdv[s][1] = bdv[s][2]; bdv[s][2] = t; int ti = biv[s][1]; biv[s][1] = biv[s][2]; biv[s][2] = ti; }
                                if (bdv[s][1] < bdv[s][0]) { float t = bdv[s][0]; bdv[s][0] = bdv[s][1]; bdv[s][1] = t; int ti = biv[s][0]; biv[s][0] = biv[s][1]; biv[s][1] = ti; }
                            }
                            acc[mt][nt][half * 2 + e] = 0.f;
                        }
                }
        }

        if (i + 2 < 16) { load_chunk(sb, i + 2, tid); CP_COMMIT(); }
    }
    __syncthreads();   // protect cand-table reuse of P buffers

    // dump per-lane top-4 (packed exact-tie-break keys): 128 rows x 16 slots x 4
    ull* tab = reinterpret_cast<ull*>(smem + OFF_PS);
    {
        const int slot = (wid >> 2) * 4 + (lane & 3);
#pragma unroll
        for (int s = 0; s < 4; ++s) {
            const int mt = s >> 1, half = s & 1;
            const int rloc = m0 + mt * 16 + half * 8 + (lane >> 2);
#pragma unroll
            for (int j = 0; j < 4; ++j)
                tab[(rloc * 16 + slot) * 4 + j] =
                    ((ull)fenc(bdv[s][j]) << 32) | (unsigned)biv[s][j];
        }
    }
    __syncthreads();

    // per-row: global top-4 of 64 keys -> exact fp32 rescore -> winner -> outputs
    const float4* z4 = reinterpret_cast<const float4*>(z);
    const float4* P4 = reinterpret_cast<const float4*>(Pf);
    float4* zh4 = reinterpret_cast<float4*>(zhat);
    float4* zt4 = reinterpret_cast<float4*>(ztil);

    for (int rr = 0; rr < 8; ++rr) {
        const int r = wid * 8 + rr;
        float4 za[4];
#pragma unroll
        for (int q = 0; q < 4; ++q)
            za[q] = z4[(size_t)(row0 + r) * 128 + q * 32 + lane];
        const float zn = s_zn[r];

        ull k0_ = tab[r * 64 + lane];
        ull k1_ = tab[r * 64 + 32 + lane];
        ull winkey = ~0ull;
#pragma unroll
        for (int it = 0; it < 4; ++it) {
            ull m = k0_ < k1_ ? k0_ : k1_;
#pragma unroll
            for (int o = 16; o; o >>= 1) {
                ull om = __shfl_xor_sync(0xffffffffu, m, o);
                m = om < m ? om : m;
            }
            const int c = (int)(m & 511ull);
            if (k0_ == m) k0_ = ~0ull;
            if (k1_ == m) k1_ = ~0ull;

            float s_ = 0.f;
#pragma unroll
            for (int q = 0; q < 4; ++q) {
                float4 pb = P4[(size_t)c * 128 + q * 32 + lane];
                s_ = fmaf(za[q].x, pb.x, s_);
                s_ = fmaf(za[q].y, pb.y, s_);
                s_ = fmaf(za[q].z, pb.z, s_);
                s_ = fmaf(za[q].w, pb.w, s_);
            }
#pragma unroll
            for (int o = 16; o; o >>= 1) s_ += __shfl_xor_sync(0xffffffffu, s_, o);
            float t = __fadd_rn(zn, s_pn[c]);
            float dist = __fadd_rn(t, -2.0f * s_);
            ull key = ((ull)fenc(dist) << 32) | (unsigned)c;
            winkey = key < winkey ? key : winkey;
        }
        const int c = (int)(winkey & 511ull);
#pragma unroll
        for (int q = 0; q < 4; ++q) {
            float4 pv = P4[(size_t)c * 128 + q * 32 + lane];
            size_t go = (size_t)(row0 + r) * 128 + q * 32 + lane;
            float4 hv;
            hv.x = __fadd_rn(__fmul_rn(0.7f, za[q].x), __fmul_rn(0.3f, pv.x));
            hv.y = __fadd_rn(__fmul_rn(0.7f, za[q].y), __fmul_rn(0.3f, pv.y));
            hv.z = __fadd_rn(__fmul_rn(0.7f, za[q].z), __fmul_rn(0.3f, pv.z));
            hv.w = __fadd_rn(__fmul_rn(0.7f, za[q].w), __fmul_rn(0.3f, pv.w));
            zt4[go] = pv;
            zh4[go] = hv;
        }
        if (lane == 0) idxf[row0 + r] = (float)c;
    }
}

extern "C" void kernel_launch(void* const* d_in, const int* in_sizes, int n_in,
                              void* d_out, int out_size)
{
    const float* z = (const float*)d_in[0];
    const float* P = (const float*)d_in[1];
    int N = in_sizes[0] / DDIM;   // 131072

    float* out  = (float*)d_out;
    float* zhat = out;
    float* ztil = out + (size_t)N * DDIM;
    float* idxf = out + 2 * (size_t)N * DDIM;

    cudaFuncSetAttribute(vq_main, cudaFuncAttributeMaxDynamicSharedMemorySize, SMEM_SZ);

    p_prep<<<KC / 8, 256>>>(P);
    vq_main<<<N / TMR, 512, SMEM_SZ>>>(z, P, zhat, ztil, idxf);
}

// round 9
// speedup vs baseline: 1.2122x; 1.0410x over previous
#include <cuda_runtime.h>
#include <cuda_bf16.h>
#include <cstdint>

#define DDIM 512
#define KC   512
#define TMR  128

// smem layout (bytes)
#define OFF_ZS  0         // 128 rows x 1024B bf16, swizzled
#define OFF_PS  131072    // 4 groups x 3 bufs x 8KB B slices; reused as 64KB cand table
#define OFF_PN  229376    // 512 f32
#define OFF_ZN  231424    // 128 f32
#define SMEM_SZ 231936

typedef unsigned long long ull;

static __device__ __align__(128) __nv_bfloat16 g_pb[KC * DDIM];
static __device__ float g_pn[KC];

__device__ __forceinline__ uint32_t smem_u32(const void* p) {
    uint32_t a;
    asm("{ .reg .u64 t; cvta.to.shared.u64 t, %1; cvt.u32.u64 %0, t; }" : "=r"(a) : "l"(p));
    return a;
}
__device__ __forceinline__ unsigned fenc(float f) {
    unsigned b = __float_as_uint(f);
    return (b & 0x80000000u) ? ~b : (b | 0x80000000u);
}
__device__ __forceinline__ uint32_t bf2(float a, float b) {
    __nv_bfloat162 h = __floats2bfloat162_rn(a, b);
    return *reinterpret_cast<uint32_t*>(&h);
}
__device__ __forceinline__ void ldsm_x4(uint32_t* r, uint32_t addr) {
    asm volatile("ldmatrix.sync.aligned.m8n8.x4.shared.b16 {%0,%1,%2,%3}, [%4];"
        : "=r"(r[0]), "=r"(r[1]), "=r"(r[2]), "=r"(r[3]) : "r"(addr));
}
__device__ __forceinline__ void mma_bf16(float* c, const uint32_t* a, uint32_t b0, uint32_t b1) {
    asm volatile("mma.sync.aligned.m16n8k16.row.col.f32.bf16.bf16.f32 "
        "{%0,%1,%2,%3}, {%4,%5,%6,%7}, {%8,%9}, {%0,%1,%2,%3};"
        : "+f"(c[0]), "+f"(c[1]), "+f"(c[2]), "+f"(c[3])
        : "r"(a[0]), "r"(a[1]), "r"(a[2]), "r"(a[3]), "r"(b0), "r"(b1));
}
#define CP_COMMIT() asm volatile("cp.async.commit_group;" ::: "memory")
#define GBAR(g) asm volatile("bar.sync %0, 128;" :: "r"((g) + 1) : "memory")

// ---------------- P prep: bf16 copy + norms ----------------
__global__ void p_prep(const float* __restrict__ P) {
    int row = blockIdx.x * 8 + (threadIdx.x >> 5);
    if (row >= KC) return;
    int lane = threadIdx.x & 31;
    const float4* pr = reinterpret_cast<const float4*>(P) + (size_t)row * 128;
    uint2* pb = reinterpret_cast<uint2*>(g_pb) + (size_t)row * 128;
    float s = 0.f;
#pragma unroll
    for (int i = 0; i < 4; ++i) {
        float4 v = pr[lane + 32 * i];
        s += v.x * v.x + v.y * v.y + v.z * v.z + v.w * v.w;
        uint2 o; o.x = bf2(v.x, v.y); o.y = bf2(v.z, v.w);
        pb[lane + 32 * i] = o;
    }
#pragma unroll
    for (int o = 16; o; o >>= 1) s += __shfl_xor_sync(0xffffffffu, s, o);
    if (lane == 0) g_pn[row] = s;
}

// ---------------- group-local B slice loader: 64 cols x 64 k = 8KB ----------------
// group g, group-thread gt (0..127): col = gt>>1 (local), half = gt&1
__device__ __forceinline__ void load_chunk(uint32_t sb, int i, int g, int gt) {
    const int ct = i >> 3, kc = i & 7, buf = i % 3;
    const int n = gt >> 1, half = gt & 1;
    const __nv_bfloat16* src = g_pb
        + (size_t)(ct * 256 + g * 64 + n) * DDIM + kc * 64 + half * 32;
    uint32_t dst = sb + OFF_PS + (uint32_t)g * 24576 + (uint32_t)buf * 8192 + n * 128;
#pragma unroll
    for (int j = 0; j < 4; ++j) {
        int c = half * 4 + j;
        uint32_t d = dst + (uint32_t)((c ^ (n & 7)) << 4);
        asm volatile("cp.async.cg.shared.global [%0], [%1], 16;"
                     :: "r"(d), "l"((const void*)(src + j * 8)) : "memory");
    }
}

// ---------------- fused main kernel: 512 threads, 4 independent 128-thr groups ----
__global__ void __launch_bounds__(512, 1) vq_main(
    const float* __restrict__ z, const float* __restrict__ Pf,
    float* __restrict__ zhat, float* __restrict__ ztil, float* __restrict__ idxf)
{
    extern __shared__ char smem[];
    const uint32_t sb = smem_u32(smem);
    const int tid = threadIdx.x, wid = tid >> 5, lane = tid & 31;
    const int row0 = blockIdx.x * TMR;
    const int m0 = (wid & 3) * 32;        // 4 m-warps x 32 rows
    const int g  = wid >> 2;              // n-group: 4 warps, 128 contiguous threads
    const int gt = tid & 127;
    const int n0 = g * 64;

    float* s_pn = reinterpret_cast<float*>(smem + OFF_PN);
    float* s_zn = reinterpret_cast<float*>(smem + OFF_ZN);

    // prefetch first B chunk before the z prologue
    load_chunk(sb, 0, g, gt);
    CP_COMMIT();

    for (int i = tid; i < KC; i += 512) s_pn[i] = g_pn[i];

    // prologue: z -> bf16 smem (swizzled), fused squared norm (4 threads/row)
    {
        const int r = tid >> 2, q = tid & 3;
        const float4* zr = reinterpret_cast<const float4*>(z)
                         + (size_t)(row0 + r) * 128 + q * 32;
        float s = 0.f;
#pragma unroll 4
        for (int c = 0; c < 16; ++c) {
            float4 v0 = zr[c * 2], v1 = zr[c * 2 + 1];
            s += v0.x * v0.x + v0.y * v0.y + v0.z * v0.z + v0.w * v0.w;
            s += v1.x * v1.x + v1.y * v1.y + v1.z * v1.z + v1.w * v1.w;
            uint4 o;
            o.x = bf2(v0.x, v0.y); o.y = bf2(v0.z, v0.w);
            o.z = bf2(v1.x, v1.y); o.w = bf2(v1.z, v1.w);
            int chunk = (q * 16 + c) ^ (r & 7);
            *reinterpret_cast<uint4*>(smem + OFF_ZS + r * 1024 + chunk * 16) = o;
        }
        s += __shfl_xor_sync(0xffffffffu, s, 1);
        s += __shfl_xor_sync(0xffffffffu, s, 2);
        if (q == 0) s_zn[r] = s;
    }

    // prime second chunk, then one CTA-wide sync for the z tile + norms
    load_chunk(sb, 1, g, gt);
    CP_COMMIT();
    __syncthreads();

    float acc[2][8][4];
    float bdv[4][4];    // per row-slot top-4 approx dists (pn - 2*dot)
    int   biv[4][4];
#pragma unroll
    for (int s = 0; s < 4; ++s)
#pragma unroll
        for (int j = 0; j < 4; ++j) { bdv[s][j] = __int_as_float(0x7f800000); biv[s][j] = j; }
#pragma unroll
    for (int mt = 0; mt < 2; ++mt)
#pragma unroll
        for (int nt = 0; nt < 8; ++nt)
#pragma unroll
            for (int e = 0; e < 4; ++e) acc[mt][nt][e] = 0.f;

    // main pipeline: 16 chunks, group-local triple buffer + group-local barrier
    for (int i = 0; i < 16; ++i) {
        if (i < 14) asm volatile("cp.async.wait_group 1;" ::: "memory");
        else        asm volatile("cp.async.wait_group 0;" ::: "memory");
        GBAR(g);

        const int ct = i >> 3, kcl = i & 7;
        const uint32_t pbase = sb + OFF_PS + (uint32_t)g * 24576
                             + (uint32_t)(i % 3) * 8192;
#pragma unroll
        for (int kk = 0; kk < 4; ++kk) {
            const int kg = kcl * 64 + kk * 16;
            uint32_t a[2][4];
#pragma unroll
            for (int mt = 0; mt < 2; ++mt) {
                int rg = m0 + mt * 16 + (lane & 15);
                int kq = kg + ((lane >> 4) << 3);
                uint32_t ad = sb + OFF_ZS + rg * 1024
                            + (uint32_t)((((kq >> 3) ^ (rg & 7))) << 4);
                ldsm_x4(a[mt], ad);
            }
#pragma unroll
            for (int ntp = 0; ntp < 4; ++ntp) {
                int nl = ntp * 16 + ((lane >> 4) << 3) + (lane & 7);   // local col
                int kq8 = kk * 2 + ((lane >> 3) & 1);
                uint32_t bdad = pbase + nl * 128
                              + (uint32_t)(((kq8 ^ (nl & 7))) << 4);
                uint32_t rb[4];
                ldsm_x4(rb, bdad);
#pragma unroll
                for (int mt = 0; mt < 2; ++mt) {
                    mma_bf16(acc[mt][ntp * 2],     a[mt], rb[0], rb[1]);
                    mma_bf16(acc[mt][ntp * 2 + 1], a[mt], rb[2], rb[3]);
                }
            }
        }

        if (kcl == 7) {
            // merge col-tile dists (pn - 2*dot; row-constant zn dropped) into top-4
            const int ctbase = ct * 256;
#pragma unroll
            for (int mt = 0; mt < 2; ++mt)
#pragma unroll
                for (int half = 0; half < 2; ++half) {
                    const int s = mt * 2 + half;
#pragma unroll
                    for (int nt = 0; nt < 8; ++nt)
#pragma unroll
                        for (int e = 0; e < 2; ++e) {
                            const int col = ctbase + n0 + nt * 8 + (lane & 3) * 2 + e;
                            float d = __fmaf_rn(-2.f, acc[mt][nt][half * 2 + e], s_pn[col]);
                            if (d < bdv[s][3]) {
                                bdv[s][3] = d; biv[s][3] = col;
                                if (bdv[s][3] < bdv[s][2]) { float t = bdv[s][2]; bdv[s][2] = bdv[s][3]; bdv[s][3] = t; int ti = biv[s][2]; biv[s][2] = biv[s][3]; biv[s][3] = ti; }
                                if (bdv[s][2] < bdv[s][1]) { float t = bdv[s][1]; bdv[s][1] = bdv[s][2]; bdv[s][2] = t; int ti = biv[s][1]; biv[s][1] = biv[s][2]; biv[s][2] = ti; }
                                if (bdv[s][1] < bdv[s][0]) { float t = bdv[s][0]; bdv[s][0] = bdv[s][1]; bdv[s][1] = t; int ti = biv[s][0]; biv[s][0] = biv[s][1]; biv[s][1] = ti; }
                            }
                            acc[mt][nt][half * 2 + e] = 0.f;
                        }
                }
        }

        if (i + 2 < 16) { load_chunk(sb, i + 2, g, gt); CP_COMMIT(); }
    }
    __syncthreads();   // all groups done before cand table overwrites B region

    // dump per-lane top-4 (packed exact-tie-break keys): 128 rows x 16 slots x 4
    ull* tab = reinterpret_cast<ull*>(smem + OFF_PS);
    {
        const int slot = g * 4 + (lane & 3);
#pragma unroll
        for (int s = 0; s < 4; ++s) {
            const int mt = s >> 1, half = s & 1;
            const int rloc = m0 + mt * 16 + half * 8 + (lane >> 2);
#pragma unroll
            for (int j = 0; j < 4; ++j)
                tab[(rloc * 16 + slot) * 4 + j] =
                    ((ull)fenc(bdv[s][j]) << 32) | (unsigned)biv[s][j];
        }
    }
    __syncthreads();

    // per-row: global top-4 of 64 keys -> exact fp32 rescore -> winner -> outputs
    const float4* z4 = reinterpret_cast<const float4*>(z);
    const float4* P4 = reinterpret_cast<const float4*>(Pf);
    float4* zh4 = reinterpret_cast<float4*>(zhat);
    float4* zt4 = reinterpret_cast<float4*>(ztil);

    for (int rr = 0; rr < 8; ++rr) {
        const int r = wid * 8 + rr;
        float4 za[4];
#pragma unroll
        for (int q = 0; q < 4; ++q)
            za[q] = z4[(size_t)(row0 + r) * 128 + q * 32 + lane];
        const float zn = s_zn[r];

        ull k0_ = tab[r * 64 + lane];
        ull k1_ = tab[r * 64 + 32 + lane];
        ull winkey = ~0ull;
#pragma unroll
        for (int it = 0; it < 4; ++it) {
            ull m = k0_ < k1_ ? k0_ : k1_;
#pragma unroll
            for (int o = 16; o; o >>= 1) {
                ull om = __shfl_xor_sync(0xffffffffu, m, o);
                m = om < m ? om : m;
            }
            const int c = (int)(m & 511ull);
            if (k0_ == m) k0_ = ~0ull;
            if (k1_ == m) k1_ = ~0ull;

            float s_ = 0.f;
#pragma unroll
            for (int q = 0; q < 4; ++q) {
                float4 pb = P4[(size_t)c * 128 + q * 32 + lane];
                s_ = fmaf(za[q].x, pb.x, s_);
                s_ = fmaf(za[q].y, pb.y, s_);
                s_ = fmaf(za[q].z, pb.z, s_);
                s_ = fmaf(za[q].w, pb.w, s_);
            }
#pragma unroll
            for (int o = 16; o; o >>= 1) s_ += __shfl_xor_sync(0xffffffffu, s_, o);
            float t = __fadd_rn(zn, s_pn[c]);
            float dist = __fadd_rn(t, -2.0f * s_);
            ull key = ((ull)fenc(dist) << 32) | (unsigned)c;
            winkey = key < winkey ? key : winkey;
        }
        const int c = (int)(winkey & 511ull);
#pragma unroll
        for (int q = 0; q < 4; ++q) {
            float4 pv = P4[(size_t)c * 128 + q * 32 + lane];
            size_t go = (size_t)(row0 + r) * 128 + q * 32 + lane;
            float4 hv;
            hv.x = __fadd_rn(__fmul_rn(0.7f, za[q].x), __fmul_rn(0.3f, pv.x));
            hv.y = __fadd_rn(__fmul_rn(0.7f, za[q].y), __fmul_rn(0.3f, pv.y));
            hv.z = __fadd_rn(__fmul_rn(0.7f, za[q].z), __fmul_rn(0.3f, pv.z));
            hv.w = __fadd_rn(__fmul_rn(0.7f, za[q].w), __fmul_rn(0.3f, pv.w));
            zt4[go] = pv;
            zh4[go] = hv;
        }
        if (lane == 0) idxf[row0 + r] = (float)c;
    }
}

extern "C" void kernel_launch(void* const* d_in, const int* in_sizes, int n_in,
                              void* d_out, int out_size)
{
    const float* z = (const float*)d_in[0];
    const float* P = (const float*)d_in[1];
    int N = in_sizes[0] / DDIM;   // 131072

    float* out  = (float*)d_out;
    float* zhat = out;
    float* ztil = out + (size_t)N * DDIM;
    float* idxf = out + 2 * (size_t)N * DDIM;

    cudaFuncSetAttribute(vq_main, cudaFuncAttributeMaxDynamicSharedMemorySize, SMEM_SZ);

    p_prep<<<KC / 8, 256>>>(P);
    vq_main<<<N / TMR, 512, SMEM_SZ>>>(z, P, zhat, ztil, idxf);
}

// round 10
// speedup vs baseline: 1.2734x; 1.0505x over previous
#include <cuda_runtime.h>
#include <cuda_bf16.h>
#include <cstdint>

#define DDIM 512
#define KC   512
#define TMR  96
#define NROWS 131072

// smem layout (bytes)
#define OFF_ZS  0         // 96 rows x 1024B bf16, swizzled
#define OFF_PS  98304     // 4 groups x 2 bufs x 16KB B slices; reused as cand table
#define OFF_PN  229376    // 512 f32
#define OFF_ZN  231424    // 96 f32
#define SMEM_SZ 231808

typedef unsigned long long ull;

static __device__ __align__(128) __nv_bfloat16 g_pb[KC * DDIM];
static __device__ float g_pn[KC];

__device__ __forceinline__ uint32_t smem_u32(const void* p) {
    uint32_t a;
    asm("{ .reg .u64 t; cvta.to.shared.u64 t, %1; cvt.u32.u64 %0, t; }" : "=r"(a) : "l"(p));
    return a;
}
__device__ __forceinline__ unsigned fenc(float f) {
    unsigned b = __float_as_uint(f);
    return (b & 0x80000000u) ? ~b : (b | 0x80000000u);
}
__device__ __forceinline__ uint32_t bf2(float a, float b) {
    __nv_bfloat162 h = __floats2bfloat162_rn(a, b);
    return *reinterpret_cast<uint32_t*>(&h);
}
__device__ __forceinline__ void ldsm_x4(uint32_t* r, uint32_t addr) {
    asm volatile("ldmatrix.sync.aligned.m8n8.x4.shared.b16 {%0,%1,%2,%3}, [%4];"
        : "=r"(r[0]), "=r"(r[1]), "=r"(r[2]), "=r"(r[3]) : "r"(addr));
}
__device__ __forceinline__ void mma_bf16(float* c, const uint32_t* a, uint32_t b0, uint32_t b1) {
    asm volatile("mma.sync.aligned.m16n8k16.row.col.f32.bf16.bf16.f32 "
        "{%0,%1,%2,%3}, {%4,%5,%6,%7}, {%8,%9}, {%0,%1,%2,%3};"
        : "+f"(c[0]), "+f"(c[1]), "+f"(c[2]), "+f"(c[3])
        : "r"(a[0]), "r"(a[1]), "r"(a[2]), "r"(a[3]), "r"(b0), "r"(b1));
}
#define CP_COMMIT() asm volatile("cp.async.commit_group;" ::: "memory")
#define GBAR(g) asm volatile("bar.sync %0, 96;" :: "r"((g) + 1) : "memory")

// ---------------- P prep: bf16 copy + norms ----------------
__global__ void p_prep(const float* __restrict__ P) {
    int row = blockIdx.x * 8 + (threadIdx.x >> 5);
    if (row >= KC) return;
    int lane = threadIdx.x & 31;
    const float4* pr = reinterpret_cast<const float4*>(P) + (size_t)row * 128;
    uint2* pb = reinterpret_cast<uint2*>(g_pb) + (size_t)row * 128;
    float s = 0.f;
#pragma unroll
    for (int i = 0; i < 4; ++i) {
        float4 v = pr[lane + 32 * i];
        s += v.x * v.x + v.y * v.y + v.z * v.z + v.w * v.w;
        uint2 o; o.x = bf2(v.x, v.y); o.y = bf2(v.z, v.w);
        pb[lane + 32 * i] = o;
    }
#pragma unroll
    for (int o = 16; o; o >>= 1) s += __shfl_xor_sync(0xffffffffu, s, o);
    if (lane == 0) g_pn[row] = s;
}

// ---- group-local B slice loader: 64 cols x 128 k = 16KB, k=128 chunk ----
// i = chunk index 0..7: ct = i>>2 (col pass), kp = i&3 (k position), buf = i&1
__device__ __forceinline__ void load_chunk(uint32_t sb, int i, int g, int gt) {
    const int ct = i >> 2, kp = i & 3, buf = i & 1;
    const uint32_t dst0 = sb + OFF_PS + (uint32_t)g * 32768 + (uint32_t)buf * 16384;
    // 1024 16B-units: unit u -> col n = u>>4, chunk c = u&15 within 256B row
#pragma unroll
    for (int u = gt; u < 1024; u += 96) {
        int n = u >> 4, c = u & 15;
        const __nv_bfloat16* src = g_pb
            + (size_t)(ct * 256 + g * 64 + n) * DDIM + kp * 128 + c * 8;
        uint32_t d = dst0 + (uint32_t)n * 256 + (uint32_t)((c ^ (n & 7)) << 4);
        asm volatile("cp.async.cg.shared.global [%0], [%1], 16;"
                     :: "r"(d), "l"((const void*)src) : "memory");
    }
}

// ------- fused main kernel: 384 threads, 12 warps = 3 m-warps x 4 n-groups -------
__global__ void __launch_bounds__(384, 1) vq_main(
    const float* __restrict__ z, const float* __restrict__ Pf,
    float* __restrict__ zhat, float* __restrict__ ztil, float* __restrict__ idxf)
{
    extern __shared__ char smem[];
    const uint32_t sb = smem_u32(smem);
    const int tid = threadIdx.x, wid = tid >> 5, lane = tid & 31;
    const int row0 = blockIdx.x * TMR;
    const int g = wid / 3;               // n-group 0..3 (warps 3g..3g+2)
    const int m_idx = wid - g * 3;       // m-warp 0..2
    const int m0 = m_idx * 32;
    const int gt = tid - g * 96;         // 0..95 within group
    const int n0 = g * 64;

    float* s_pn = reinterpret_cast<float*>(smem + OFF_PN);
    float* s_zn = reinterpret_cast<float*>(smem + OFF_ZN);

    // prefetch first B chunk (group-local) before the z prologue
    load_chunk(sb, 0, g, gt);
    CP_COMMIT();

    for (int i = tid; i < KC; i += 384) s_pn[i] = g_pn[i];

    // prologue: z -> bf16 smem (swizzled), fused squared norm (4 threads/row)
    {
        const int r = tid >> 2, q = tid & 3;
        const int zrow = min(row0 + r, NROWS - 1);     // clamp for partial last CTA
        const float4* zr = reinterpret_cast<const float4*>(z)
                         + (size_t)zrow * 128 + q * 32;
        float s = 0.f;
#pragma unroll 4
        for (int c = 0; c < 16; ++c) {
            float4 v0 = zr[c * 2], v1 = zr[c * 2 + 1];
            s += v0.x * v0.x + v0.y * v0.y + v0.z * v0.z + v0.w * v0.w;
            s += v1.x * v1.x + v1.y * v1.y + v1.z * v1.z + v1.w * v1.w;
            uint4 o;
            o.x = bf2(v0.x, v0.y); o.y = bf2(v0.z, v0.w);
            o.z = bf2(v1.x, v1.y); o.w = bf2(v1.z, v1.w);
            int chunk = (q * 16 + c) ^ (r & 7);
            *reinterpret_cast<uint4*>(smem + OFF_ZS + r * 1024 + chunk * 16) = o;
        }
        s += __shfl_xor_sync(0xffffffffu, s, 1);
        s += __shfl_xor_sync(0xffffffffu, s, 2);
        if (q == 0) s_zn[r] = s;
    }
    __syncthreads();       // z tile + norms visible to all

    float acc[2][8][4];
    float bdv[4][4];       // per row-slot top-4 approx dists (pn - 2*dot)
    int   biv[4][4];
#pragma unroll
    for (int s = 0; s < 4; ++s)
#pragma unroll
        for (int j = 0; j < 4; ++j) { bdv[s][j] = __int_as_float(0x7f800000); biv[s][j] = j; }
#pragma unroll
    for (int mt = 0; mt < 2; ++mt)
#pragma unroll
        for (int nt = 0; nt < 8; ++nt)
#pragma unroll
            for (int e = 0; e < 4; ++e) acc[mt][nt][e] = 0.f;

    // main pipeline: 8 chunks = 2 col-passes x 4 k-chunks (k=128), double-buffered
    for (int i = 0; i < 8; ++i) {
        asm volatile("cp.async.wait_group 0;" ::: "memory");
        GBAR(g);
        if (i < 7) { load_chunk(sb, i + 1, g, gt); CP_COMMIT(); }

        const int ct = i >> 2, kp = i & 3;
        const uint32_t pbase = sb + OFF_PS + (uint32_t)g * 32768
                             + (uint32_t)(i & 1) * 16384;
#pragma unroll
        for (int kk = 0; kk < 8; ++kk) {
            const int kg = kp * 128 + kk * 16;
            uint32_t a[2][4];
#pragma unroll
            for (int mt = 0; mt < 2; ++mt) {
                int rg = m0 + mt * 16 + (lane & 15);
                int kq = kg + ((lane >> 4) << 3);
                uint32_t ad = sb + OFF_ZS + rg * 1024
                            + (uint32_t)((((kq >> 3) ^ (rg & 7))) << 4);
                ldsm_x4(a[mt], ad);
            }
#pragma unroll
            for (int ntp = 0; ntp < 4; ++ntp) {
                int nl = ntp * 16 + ((lane >> 4) << 3) + (lane & 7);   // local col
                int kq8 = kk * 2 + ((lane >> 3) & 1);                  // 16B chunk 0..15
                uint32_t bdad = pbase + (uint32_t)nl * 256
                              + (uint32_t)(((kq8 ^ (nl & 7))) << 4);
                uint32_t rb[4];
                ldsm_x4(rb, bdad);
#pragma unroll
                for (int mt = 0; mt < 2; ++mt) {
                    mma_bf16(acc[mt][ntp * 2],     a[mt], rb[0], rb[1]);
                    mma_bf16(acc[mt][ntp * 2 + 1], a[mt], rb[2], rb[3]);
                }
            }
        }

        if (kp == 3) {
            // merge col-pass dists (pn - 2*dot; row-constant zn dropped) into top-4
            const int ctbase = ct * 256;
#pragma unroll
            for (int mt = 0; mt < 2; ++mt)
#pragma unroll
                for (int half = 0; half < 2; ++half) {
                    const int s = mt * 2 + half;
#pragma unroll
                    for (int nt = 0; nt < 8; ++nt)
#pragma unroll
                        for (int e = 0; e < 2; ++e) {
                            const int col = ctbase + n0 + nt * 8 + (lane & 3) * 2 + e;
                            float d = __fmaf_rn(-2.f, acc[mt][nt][half * 2 + e], s_pn[col]);
                            if (d < bdv[s][3]) {
                                bdv[s][3] = d; biv[s][3] = col;
                                if (bdv[s][3] < bdv[s][2]) { float t = bdv[s][2]; bdv[s][2] = bdv[s][3]; bdv[s][3] = t; int ti = biv[s][2]; biv[s][2] = biv[s][3]; biv[s][3] = ti; }
                                if (bdv[s][2] < bdv[s][1]) { float t = bdv[s][1]; bdv[s][1] = bdv[s][2]; bdv[s][2] = t; int ti = biv[s][1]; biv[s][1] = biv[s][2]; biv[s][2] = ti; }
                                if (bdv[s][1] < bdv[s][0]) { float t = bdv[s][0]; bdv[s][0] = bdv[s][1]; bdv[s][1] = t; int ti = biv[s][0]; biv[s][0] = biv[s][1]; biv[s][1] = ti; }
                            }
                            acc[mt][nt][half * 2 + e] = 0.f;
                        }
                }
        }
    }
    __syncthreads();   // all groups done before cand table overwrites B region

    // dump per-lane top-4 (packed exact-tie-break keys): 96 rows x 16 slots x 4
    ull* tab = reinterpret_cast<ull*>(smem + OFF_PS);
    {
        const int slot = g * 4 + (lane & 3);
#pragma unroll
        for (int s = 0; s < 4; ++s) {
            const int mt = s >> 1, half = s & 1;
            const int rloc = m0 + mt * 16 + half * 8 + (lane >> 2);
#pragma unroll
            for (int j = 0; j < 4; ++j)
                tab[(rloc * 16 + slot) * 4 + j] =
                    ((ull)fenc(bdv[s][j]) << 32) | (unsigned)biv[s][j];
        }
    }
    __syncthreads();

    // per-row: global top-4 of 64 keys -> exact fp32 rescore -> winner -> outputs
    const float4* z4 = reinterpret_cast<const float4*>(z);
    const float4* P4 = reinterpret_cast<const float4*>(Pf);
    float4* zh4 = reinterpret_cast<float4*>(zhat);
    float4* zt4 = reinterpret_cast<float4*>(ztil);

    for (int rr = 0; rr < 8; ++rr) {
        const int r = wid * 8 + rr;
        const int zrow = row0 + r;
        const int zc = min(zrow, NROWS - 1);
        float4 za[4];
#pragma unroll
        for (int q = 0; q < 4; ++q)
            za[q] = z4[(size_t)zc * 128 + q * 32 + lane];
        const float zn = s_zn[r];

        ull k0_ = tab[r * 64 + lane];
        ull k1_ = tab[r * 64 + 32 + lane];
        ull winkey = ~0ull;
#pragma unroll
        for (int it = 0; it < 4; ++it) {
            ull m = k0_ < k1_ ? k0_ : k1_;
#pragma unroll
            for (int o = 16; o; o >>= 1) {
                ull om = __shfl_xor_sync(0xffffffffu, m, o);
                m = om < m ? om : m;
            }
            const int c = (int)(m & 511ull);
            if (k0_ == m) k0_ = ~0ull;
            if (k1_ == m) k1_ = ~0ull;

            float s_ = 0.f;
#pragma unroll
            for (int q = 0; q < 4; ++q) {
                float4 pb = P4[(size_t)c * 128 + q * 32 + lane];
                s_ = fmaf(za[q].x, pb.x, s_);
                s_ = fmaf(za[q].y, pb.y, s_);
                s_ = fmaf(za[q].z, pb.z, s_);
                s_ = fmaf(za[q].w, pb.w, s_);
            }
#pragma unroll
            for (int o = 16; o; o >>= 1) s_ += __shfl_xor_sync(0xffffffffu, s_, o);
            float t = __fadd_rn(zn, s_pn[c]);
            float dist = __fadd_rn(t, -2.0f * s_);
            ull key = ((ull)fenc(dist) << 32) | (unsigned)c;
            winkey = key < winkey ? key : winkey;
        }
        if (zrow < NROWS) {
            const int c = (int)(winkey & 511ull);
#pragma unroll
            for (int q = 0; q < 4; ++q) {
                float4 pv = P4[(size_t)c * 128 + q * 32 + lane];
                size_t go = (size_t)zrow * 128 + q * 32 + lane;
                float4 hv;
                hv.x = __fadd_rn(__fmul_rn(0.7f, za[q].x), __fmul_rn(0.3f, pv.x));
                hv.y = __fadd_rn(__fmul_rn(0.7f, za[q].y), __fmul_rn(0.3f, pv.y));
                hv.z = __fadd_rn(__fmul_rn(0.7f, za[q].z), __fmul_rn(0.3f, pv.z));
                hv.w = __fadd_rn(__fmul_rn(0.7f, za[q].w), __fmul_rn(0.3f, pv.w));
                zt4[go] = pv;
                zh4[go] = hv;
            }
            if (lane == 0) idxf[zrow] = (float)c;
        }
    }
}

extern "C" void kernel_launch(void* const* d_in, const int* in_sizes, int n_in,
                              void* d_out, int out_size)
{
    const float* z = (const float*)d_in[0];
    const float* P = (const float*)d_in[1];
    int N = in_sizes[0] / DDIM;   // 131072

    float* out  = (float*)d_out;
    float* zhat = out;
    float* ztil = out + (size_t)N * DDIM;
    float* idxf = out + 2 * (size_t)N * DDIM;

    cudaFuncSetAttribute(vq_main, cudaFuncAttributeMaxDynamicSharedMemorySize, SMEM_SZ);

    p_prep<<<KC / 8, 256>>>(P);
    vq_main<<<(N + TMR - 1) / TMR, 384, SMEM_SZ>>>(z, P, zhat, ztil, idxf);
}